// round 12
// baseline (speedup 1.0000x reference)
#include <cuda_runtime.h>
#include <cstdint>

// Shape constants (fixed by the reference problem)
namespace icr {
constexpr int kB = 16;
constexpr int kS = 4096;
constexpr int kD = 1024;
constexpr int kDVec = kD / 4;          // 256 float4 per weight row
constexpr int kWarps = 2;
constexpr int kThreads = kWarps * 32;  // 64
constexpr int kTokPerWarp = 8;
constexpr int kTokPerCta = kWarps * kTokPerWarp;  // 16
constexpr int kBatch = 4;              // tokens per deferred-reduction batch
}  // namespace icr

__global__ void icr_zero(float* __restrict__ o, int n) {
    int i = blockIdx.x * blockDim.x + threadIdx.x;
    if (i < n) o[i] = 0.0f;
}

__global__ __launch_bounds__(icr::kThreads)
void icr_main(const float*  __restrict__ x,        // (B,S,D)
              const float*  __restrict__ Wmat,     // (2,D)
              const float*  __restrict__ bvec,     // (2,)
              const int*    __restrict__ lens,     // (B,)
              float*        __restrict__ o)        // (B,)
{
    using namespace icr;

    const int b    = blockIdx.y;
    const int len  = lens[b];
    const int s0   = blockIdx.x * kTokPerCta;
    if (s0 >= len) return;                          // 16-token early-exit quantum

    __shared__ float4 sw0[kDVec];
    __shared__ float4 sw1[kDVec];

    const int tid  = threadIdx.x;
    const int wid  = tid >> 5;
    const int lane = tid & 31;

    const float bias0 = bvec[0];
    const float bias1 = bvec[1];

    // Stage the two weight rows into shared (64 thr x 4 float4 each)
    {
        const float4* w0g = reinterpret_cast<const float4*>(Wmat);
        const float4* w1g = reinterpret_cast<const float4*>(Wmat + kD);
        #pragma unroll 4
        for (int k = 0; k < 4; ++k) {
            sw0[tid + 64 * k] = w0g[tid + 64 * k];
            sw1[tid + 64 * k] = w1g[tid + 64 * k];
        }
    }
    __syncthreads();

    const float* xrow0 = x + (size_t)b * kS * kD;
    const int    wbase = s0 + wid * kTokPerWarp;

    float acc = 0.0f;                               // per-lane partial (lanes 0-3)

    #pragma unroll
    for (int seg = 0; seg < kTokPerWarp / kBatch; ++seg) {
        const int tb = wbase + seg * kBatch;
        if (tb >= len) break;                       // uniform across the warp

        // Rows tb..tb+3 always lie inside x (tb <= 4092); validity is applied
        // only when contributions are added. Loads are branch-free.
        const float4* r = reinterpret_cast<const float4*>(xrow0 + (size_t)tb * kD);

        float dg[kBatch] = {0.f, 0.f, 0.f, 0.f};    // gate-dot partials
        float dr[kBatch] = {0.f, 0.f, 0.f, 0.f};    // reward-dot partials

        #pragma unroll
        for (int k = 0; k < 8; ++k) {
            const int idx = lane + 32 * k;          // coalesced across lanes
            const float4 w0 = sw0[idx];
            const float4 w1 = sw1[idx];
            #pragma unroll
            for (int t = 0; t < kBatch; ++t) {
                float4 v = __ldcs(&r[(size_t)t * kDVec + idx]);
                dg[t] += v.x * w0.x + v.y * w0.y + v.z * w0.z + v.w * w0.w;
                dr[t] += v.x * w1.x + v.y * w1.y + v.z * w1.z + v.w * w1.w;
            }
        }

        // 8 interleaved butterfly chains: SHFL latency of each chain hides
        // under the other seven (amortized ~40 cy per token).
        #pragma unroll
        for (int off = 16; off > 0; off >>= 1) {
            #pragma unroll
            for (int t = 0; t < kBatch; ++t) {
                dg[t] += __shfl_xor_sync(0xFFFFFFFFu, dg[t], off);
                dr[t] += __shfl_xor_sync(0xFFFFFFFFu, dr[t], off);
            }
        }

        // All lanes hold all 8 sums; lanes 0-3 finish one token each
        // (parallel sigmoids, no single-lane serialization).
        if (lane < kBatch && (tb + lane) < len) {
            float f0 = bias0, f1 = bias1;
            #pragma unroll
            for (int t = 0; t < kBatch; ++t) {
                if (t == lane) { f0 += dg[t]; f1 += dr[t]; }
            }
            acc += f1 * (1.0f / (1.0f + __expf(-f0)));
        }
    }

    // Tail: partials live only in lanes 0-3 -> 2-stage reduce + 1 atomic/warp
    acc += __shfl_xor_sync(0xFFFFFFFFu, acc, 2);
    acc += __shfl_xor_sync(0xFFFFFFFFu, acc, 1);
    if (lane == 0) atomicAdd(&o[b], acc);
}

extern "C" void kernel_launch(void* const* d_in, const int* in_sizes, int n_in,
                              void* d_out, int out_size) {
    const float* x    = (const float*)d_in[0];   // (B,S,D) fp32
    const float* Wmat = (const float*)d_in[1];   // (2,D)   fp32
    const float* bvec = (const float*)d_in[2];   // (2,)    fp32
    const int*   lens = (const int*)d_in[3];     // (B,)    int32
    float*       o    = (float*)d_out;           // (B,)    fp32

    icr_zero<<<1, 32>>>(o, out_size);

    dim3 grid(icr::kS / icr::kTokPerCta, icr::kB);   // (256, 16)
    icr_main<<<grid, icr::kThreads>>>(x, Wmat, bvec, lens, o);
}